// round 1
// baseline (speedup 1.0000x reference)
#include <cuda_runtime.h>
#include <math.h>

#define N_MET   100000
#define N_RXN   200000
#define E_SUB   400000
#define E_PROD  400000
#define HIDDEN  128
#define MSG     64
#define DT      0.01f

// ---------------- scratch (device globals; no allocation allowed) -------------
__device__ float g_hrxn[(size_t)N_RXN * MSG];   // 51.2 MB: per-rxn message accum
__device__ float g_extns[2 * N_RXN];            // interleaved {ext_agg, n_sub}
__device__ float g_v[N_RXN];                    // reaction rate (pre/post scale)
__device__ float g_rscale[N_RXN];               // per-rxn min scale (float bits, atomicMin as int)
__device__ float g_totcons[N_MET];
__device__ float g_mscale[N_MET];

// ---------------- helpers -----------------------------------------------------
__device__ __forceinline__ void red_add_v4(float* p, float a, float b, float c, float d) {
    asm volatile("red.global.add.v4.f32 [%0], {%1,%2,%3,%4};"
                 :: "l"(p), "f"(a), "f"(b), "f"(c), "f"(d) : "memory");
}
__device__ __forceinline__ void red_add_v2(float* p, float a, float b) {
    asm volatile("red.global.add.v2.f32 [%0], {%1,%2};"
                 :: "l"(p), "f"(a), "f"(b) : "memory");
}

// ---------------- K0: init ----------------------------------------------------
__global__ void k_init(float* __restrict__ out) {
    int i = blockIdx.x * blockDim.x + threadIdx.x;
    int stride = gridDim.x * blockDim.x;
    float4 z4 = make_float4(0.f, 0.f, 0.f, 0.f);
    float4* h4 = reinterpret_cast<float4*>(g_hrxn);
    const int NH4 = N_RXN * MSG / 4;
    for (int p = i; p < NH4; p += stride) h4[p] = z4;
    for (int p = i; p < 2 * N_RXN; p += stride) g_extns[p] = 0.f;
    for (int p = i; p < N_MET; p += stride) { g_totcons[p] = 0.f; out[p] = 0.f; }
}

// ---------------- K1: edge MLP + scatter into h_rxn ---------------------------
__global__ __launch_bounds__(128)
void k_edge_mlp(const float* __restrict__ x,
                const int*   __restrict__ met_sub,
                const int*   __restrict__ rxn_sub,
                const float* __restrict__ sto_sub,
                const float* __restrict__ W1,
                const float* __restrict__ b1,
                const float* __restrict__ W2,
                const float* __restrict__ b2)
{
    __shared__ float sU[HIDDEN], sW[HIDDEN], sB[HIDDEN];
    __shared__ float sW2[HIDDEN * MSG];   // [j][k], k contiguous
    __shared__ float sB2[MSG];

    for (int i = threadIdx.x; i < HIDDEN; i += blockDim.x) {
        sU[i] = W1[i];
        sW[i] = W1[HIDDEN + i];
        sB[i] = b1[i];
    }
    for (int i = threadIdx.x; i < HIDDEN * MSG / 4; i += blockDim.x)
        reinterpret_cast<float4*>(sW2)[i] = reinterpret_cast<const float4*>(W2)[i];
    for (int i = threadIdx.x; i < MSG; i += blockDim.x) sB2[i] = b2[i];
    __syncthreads();

    int e = blockIdx.x * blockDim.x + threadIdx.x;
    if (e >= E_SUB) return;

    int   m   = met_sub[e];
    int   r   = rxn_sub[e];
    float s   = sto_sub[e];
    float a   = x[m * 8 + 3];   // conc
    float ext = x[m * 8 + 4];   // ext

    float msg[MSG];
    #pragma unroll
    for (int k = 0; k < MSG; k++) msg[k] = sB2[k];

    #pragma unroll 2
    for (int j = 0; j < HIDDEN; j++) {
        float h = tanhf(fmaf(a, sU[j], fmaf(s, sW[j], sB[j])));
        const float4* w2r = reinterpret_cast<const float4*>(sW2 + j * MSG);
        #pragma unroll
        for (int k4 = 0; k4 < MSG / 4; k4++) {
            float4 w = w2r[k4];
            msg[4*k4+0] = fmaf(h, w.x, msg[4*k4+0]);
            msg[4*k4+1] = fmaf(h, w.y, msg[4*k4+1]);
            msg[4*k4+2] = fmaf(h, w.z, msg[4*k4+2]);
            msg[4*k4+3] = fmaf(h, w.w, msg[4*k4+3]);
        }
    }

    float* dst = g_hrxn + (size_t)r * MSG;
    #pragma unroll
    for (int k4 = 0; k4 < MSG / 4; k4++)
        red_add_v4(dst + 4*k4, msg[4*k4+0], msg[4*k4+1], msg[4*k4+2], msg[4*k4+3]);

    red_add_v2(g_extns + 2 * r, ext, 1.0f);
}

// ---------------- K2: reaction MLP -> v_pre; init rxn_scale -------------------
__global__ __launch_bounds__(128)
void k_rxn_mlp(const float* __restrict__ V1,
               const float* __restrict__ c1,
               const float* __restrict__ V2,
               const float* __restrict__ c2,
               const float* __restrict__ log_k)
{
    __shared__ float sV1t[HIDDEN * MSG];  // transposed: [j][k], k contiguous
    __shared__ float sC1[HIDDEN];
    __shared__ float sV2[HIDDEN];

    for (int i = threadIdx.x; i < HIDDEN * MSG; i += blockDim.x) {
        int j = i / MSG, k = i % MSG;
        sV1t[i] = V1[k * HIDDEN + j];     // V1 shape [MSG][HIDDEN]
    }
    for (int i = threadIdx.x; i < HIDDEN; i += blockDim.x) {
        sC1[i] = c1[i];
        sV2[i] = V2[i];
    }
    __syncthreads();

    int r = blockIdx.x * blockDim.x + threadIdx.x;
    if (r >= N_RXN) return;

    float h[MSG];
    const float4* hp = reinterpret_cast<const float4*>(g_hrxn + (size_t)r * MSG);
    #pragma unroll
    for (int i = 0; i < MSG / 4; i++) {
        float4 t = hp[i];
        h[4*i+0] = t.x; h[4*i+1] = t.y; h[4*i+2] = t.z; h[4*i+3] = t.w;
    }

    float acc = 0.f;
    #pragma unroll 2
    for (int j = 0; j < HIDDEN; j++) {
        float t = sC1[j];
        const float4* vr = reinterpret_cast<const float4*>(sV1t + j * MSG);
        #pragma unroll
        for (int k4 = 0; k4 < MSG / 4; k4++) {
            float4 w = vr[k4];
            t = fmaf(h[4*k4+0], w.x, t);
            t = fmaf(h[4*k4+1], w.y, t);
            t = fmaf(h[4*k4+2], w.z, t);
            t = fmaf(h[4*k4+3], w.w, t);
        }
        acc = fmaf(tanhf(t), sV2[j], acc);
    }

    float z    = acc + c2[0];
    float base = fmaxf(z, 0.f) + log1pf(expf(-fabsf(z)));  // softplus, stable
    float k10  = exp10f(log_k[r]);
    float ea   = g_extns[2 * r];
    float ns   = fmaxf(g_extns[2 * r + 1], 1.0f);
    g_v[r]      = k10 * (ea / ns) * base;
    g_rscale[r] = 1.0f;
}

// ---------------- K3a: total consumption per metabolite -----------------------
__global__ void k_totcons(const int* __restrict__ met_sub,
                          const int* __restrict__ rxn_sub,
                          const float* __restrict__ sto_sub)
{
    int e = blockIdx.x * blockDim.x + threadIdx.x;
    if (e >= E_SUB) return;
    float c = sto_sub[e] * g_v[rxn_sub[e]] * DT;
    atomicAdd(&g_totcons[met_sub[e]], c);
}

// ---------------- K3b: per-met scale ------------------------------------------
__global__ void k_mscale(const float* __restrict__ x)
{
    int m = blockIdx.x * blockDim.x + threadIdx.x;
    if (m >= N_MET) return;
    float tot  = g_totcons[m];
    float conc = x[m * 8 + 3];
    g_mscale[m] = (tot > 1e-12f) ? fminf(conc / tot, 1.0f) : 1.0f;
}

// ---------------- K3c: per-rxn min scale (int-bits atomicMin, vals in [0,1]) --
__global__ void k_rscale(const int* __restrict__ met_sub,
                         const int* __restrict__ rxn_sub)
{
    int e = blockIdx.x * blockDim.x + threadIdx.x;
    if (e >= E_SUB) return;
    int bits = __float_as_int(g_mscale[met_sub[e]]);
    atomicMin(reinterpret_cast<int*>(&g_rscale[rxn_sub[e]]), bits);
}

// ---------------- K4a: apply scale --------------------------------------------
__global__ void k_vscale()
{
    int r = blockIdx.x * blockDim.x + threadIdx.x;
    if (r >= N_RXN) return;
    g_v[r] *= g_rscale[r];
}

// ---------------- K4b: signed contributions -> dxdt ---------------------------
__global__ void k_contrib(const int* __restrict__ met_sub,
                          const int* __restrict__ rxn_sub,
                          const float* __restrict__ sto_sub,
                          const int* __restrict__ met_prod,
                          const int* __restrict__ rxn_prod,
                          const float* __restrict__ sto_prod,
                          float* __restrict__ out)
{
    int i = blockIdx.x * blockDim.x + threadIdx.x;
    if (i >= E_SUB + E_PROD) return;
    int m; float c;
    if (i < E_SUB) {
        m = met_sub[i];
        c = -sto_sub[i] * g_v[rxn_sub[i]];
    } else {
        int e = i - E_SUB;
        m = met_prod[e];
        c = sto_prod[e] * g_v[rxn_prod[e]];
    }
    atomicAdd(&out[m], c);
}

// ---------------- launch ------------------------------------------------------
extern "C" void kernel_launch(void* const* d_in, const int* in_sizes, int n_in,
                              void* d_out, int out_size)
{
    const float* x        = (const float*)d_in[0];
    const int*   met_sub  = (const int*)  d_in[1];
    const int*   rxn_sub  = (const int*)  d_in[2];
    const float* sto_sub  = (const float*)d_in[3];
    const int*   met_prod = (const int*)  d_in[4];
    const int*   rxn_prod = (const int*)  d_in[5];
    const float* sto_prod = (const float*)d_in[6];
    const float* W1       = (const float*)d_in[7];
    const float* b1       = (const float*)d_in[8];
    const float* W2       = (const float*)d_in[9];
    const float* b2       = (const float*)d_in[10];
    const float* V1       = (const float*)d_in[11];
    const float* c1       = (const float*)d_in[12];
    const float* V2       = (const float*)d_in[13];
    const float* c2       = (const float*)d_in[14];
    const float* log_k    = (const float*)d_in[15];
    float* out = (float*)d_out;

    k_init<<<2048, 256>>>(out);

    k_edge_mlp<<<(E_SUB + 127) / 128, 128>>>(x, met_sub, rxn_sub, sto_sub, W1, b1, W2, b2);

    k_rxn_mlp<<<(N_RXN + 127) / 128, 128>>>(V1, c1, V2, c2, log_k);

    k_totcons<<<(E_SUB + 255) / 256, 256>>>(met_sub, rxn_sub, sto_sub);

    k_mscale<<<(N_MET + 255) / 256, 256>>>(x);

    k_rscale<<<(E_SUB + 255) / 256, 256>>>(met_sub, rxn_sub);

    k_vscale<<<(N_RXN + 255) / 256, 256>>>();

    k_contrib<<<(E_SUB + E_PROD + 255) / 256, 256>>>(
        met_sub, rxn_sub, sto_sub, met_prod, rxn_prod, sto_prod, out);
}

// round 2
// speedup vs baseline: 1.0094x; 1.0094x over previous
#include <cuda_runtime.h>
#include <math.h>

#define N_MET   100000
#define N_RXN   200000
#define E_SUB   400000
#define E_PROD  400000
#define HIDDEN  128
#define MSG     64
#define DT      0.01f

typedef unsigned long long u64;

// ---------------- scratch (device globals; no allocation allowed) -------------
__device__ float g_hrxn[(size_t)N_RXN * MSG];   // 51.2 MB: per-rxn message accum
__device__ float g_extns[2 * N_RXN];            // interleaved {ext_agg, n_sub}
__device__ float g_v[N_RXN];                    // reaction rate (pre-scale)
__device__ float g_rscale[N_RXN];               // per-rxn min scale (pos floats: int-min == float-min)
__device__ float g_totcons[N_MET];

// ---------------- helpers -----------------------------------------------------
__device__ __forceinline__ void red_add_v4(float* p, float a, float b, float c, float d) {
    asm volatile("red.global.add.v4.f32 [%0], {%1,%2,%3,%4};"
                 :: "l"(p), "f"(a), "f"(b), "f"(c), "f"(d) : "memory");
}
__device__ __forceinline__ void red_add_v2(float* p, float a, float b) {
    asm volatile("red.global.add.v2.f32 [%0], {%1,%2};"
                 :: "l"(p), "f"(a), "f"(b) : "memory");
}
__device__ __forceinline__ u64 pack2(float lo, float hi) {
    u64 r; asm("mov.b64 %0, {%1,%2};" : "=l"(r) : "f"(lo), "f"(hi)); return r;
}
__device__ __forceinline__ void unpack2(u64 v, float& lo, float& hi) {
    asm("mov.b64 {%0,%1}, %2;" : "=f"(lo), "=f"(hi) : "l"(v));
}
__device__ __forceinline__ u64 fma2(u64 a, u64 b, u64 c) {
    u64 d; asm("fma.rn.f32x2 %0, %1, %2, %3;" : "=l"(d) : "l"(a), "l"(b), "l"(c)); return d;
}
__device__ __forceinline__ float tanh_fast(float x) {
    float y; asm("tanh.approx.f32 %0, %1;" : "=f"(y) : "f"(x)); return y;
}

// ---------------- K0: init ----------------------------------------------------
__global__ void k_init(float* __restrict__ out) {
    int i = blockIdx.x * blockDim.x + threadIdx.x;
    int stride = gridDim.x * blockDim.x;
    float4 z4 = make_float4(0.f, 0.f, 0.f, 0.f);
    float4* h4 = reinterpret_cast<float4*>(g_hrxn);
    const int NH4 = N_RXN * MSG / 4;
    for (int p = i; p < NH4; p += stride) h4[p] = z4;
    for (int p = i; p < 2 * N_RXN; p += stride) g_extns[p] = 0.f;
    for (int p = i; p < N_MET; p += stride) { g_totcons[p] = 0.f; out[p] = 0.f; }
}

// ---------------- K1: edge MLP + scatter into h_rxn ---------------------------
__global__ __launch_bounds__(128)
void k_edge_mlp(const float* __restrict__ x,
                const int*   __restrict__ met_sub,
                const int*   __restrict__ rxn_sub,
                const float* __restrict__ sto_sub,
                const float* __restrict__ W1,
                const float* __restrict__ b1,
                const float* __restrict__ W2,
                const float* __restrict__ b2)
{
    __shared__ float sU[HIDDEN], sW[HIDDEN], sB[HIDDEN];
    __shared__ __align__(16) float sW2[HIDDEN * MSG];   // [j][k], k contiguous
    __shared__ __align__(16) float sB2[MSG];

    for (int i = threadIdx.x; i < HIDDEN; i += blockDim.x) {
        sU[i] = W1[i];
        sW[i] = W1[HIDDEN + i];
        sB[i] = b1[i];
    }
    for (int i = threadIdx.x; i < HIDDEN * MSG / 4; i += blockDim.x)
        reinterpret_cast<float4*>(sW2)[i] = reinterpret_cast<const float4*>(W2)[i];
    for (int i = threadIdx.x; i < MSG; i += blockDim.x) sB2[i] = b2[i];
    __syncthreads();

    int e = blockIdx.x * blockDim.x + threadIdx.x;
    if (e >= E_SUB) return;

    int   m   = met_sub[e];
    int   r   = rxn_sub[e];
    float s   = sto_sub[e];
    float a   = x[m * 8 + 3];   // conc
    float ext = x[m * 8 + 4];   // ext

    // packed accumulators: 32 x f32x2 = 64 floats
    u64 msg2[MSG / 2];
    {
        const u64* b2p = reinterpret_cast<const u64*>(sB2);
        #pragma unroll
        for (int p = 0; p < MSG / 2; p++) msg2[p] = b2p[p];
    }

    #pragma unroll 2
    for (int j = 0; j < HIDDEN; j++) {
        float h = tanh_fast(fmaf(a, sU[j], fmaf(s, sW[j], sB[j])));
        u64 h2 = pack2(h, h);
        const ulonglong2* w2r = reinterpret_cast<const ulonglong2*>(sW2 + j * MSG);
        #pragma unroll
        for (int p = 0; p < MSG / 4; p++) {
            ulonglong2 w = w2r[p];
            msg2[2*p+0] = fma2(h2, w.x, msg2[2*p+0]);
            msg2[2*p+1] = fma2(h2, w.y, msg2[2*p+1]);
        }
    }

    float* dst = g_hrxn + (size_t)r * MSG;
    #pragma unroll
    for (int p = 0; p < MSG / 4; p++) {
        float m0, m1, m2, m3;
        unpack2(msg2[2*p+0], m0, m1);
        unpack2(msg2[2*p+1], m2, m3);
        red_add_v4(dst + 4*p, m0, m1, m2, m3);
    }

    red_add_v2(g_extns + 2 * r, ext, 1.0f);
}

// ---------------- K2: reaction MLP -> v_pre; init rxn_scale -------------------
__global__ __launch_bounds__(128)
void k_rxn_mlp(const float* __restrict__ V1,
               const float* __restrict__ c1,
               const float* __restrict__ V2,
               const float* __restrict__ c2,
               const float* __restrict__ log_k)
{
    __shared__ __align__(16) float sV1t[HIDDEN * MSG];  // transposed: [j][k], k contiguous
    __shared__ float sC1[HIDDEN];
    __shared__ float sV2[HIDDEN];

    for (int i = threadIdx.x; i < HIDDEN * MSG; i += blockDim.x) {
        int j = i / MSG, k = i % MSG;
        sV1t[i] = V1[k * HIDDEN + j];     // V1 shape [MSG][HIDDEN]
    }
    for (int i = threadIdx.x; i < HIDDEN; i += blockDim.x) {
        sC1[i] = c1[i];
        sV2[i] = V2[i];
    }
    __syncthreads();

    int r = blockIdx.x * blockDim.x + threadIdx.x;
    if (r >= N_RXN) return;

    u64 h2[MSG / 2];
    {
        const ulonglong2* hp = reinterpret_cast<const ulonglong2*>(g_hrxn + (size_t)r * MSG);
        #pragma unroll
        for (int p = 0; p < MSG / 4; p++) {
            ulonglong2 t = hp[p];
            h2[2*p+0] = t.x;
            h2[2*p+1] = t.y;
        }
    }

    float acc = 0.f;
    #pragma unroll 2
    for (int j = 0; j < HIDDEN; j++) {
        u64 t2 = 0ull;  // {0,0}
        const ulonglong2* vr = reinterpret_cast<const ulonglong2*>(sV1t + j * MSG);
        #pragma unroll
        for (int p = 0; p < MSG / 4; p++) {
            ulonglong2 w = vr[p];
            t2 = fma2(h2[2*p+0], w.x, t2);
            t2 = fma2(h2[2*p+1], w.y, t2);
        }
        float tl, th;
        unpack2(t2, tl, th);
        float t = sC1[j] + tl + th;
        acc = fmaf(tanh_fast(t), sV2[j], acc);
    }

    float z    = acc + c2[0];
    float base = fmaxf(z, 0.f) + log1pf(expf(-fabsf(z)));  // softplus, stable
    float k10  = exp10f(log_k[r]);
    float ea   = g_extns[2 * r];
    float ns   = fmaxf(g_extns[2 * r + 1], 1.0f);
    g_v[r]      = k10 * (ea / ns) * base;
    g_rscale[r] = 1.0f;
}

// ---------------- K3a: total consumption per metabolite -----------------------
__global__ void k_totcons(const int* __restrict__ met_sub,
                          const int* __restrict__ rxn_sub,
                          const float* __restrict__ sto_sub)
{
    int e = blockIdx.x * blockDim.x + threadIdx.x;
    if (e >= E_SUB) return;
    float c = sto_sub[e] * g_v[rxn_sub[e]] * DT;
    atomicAdd(&g_totcons[met_sub[e]], c);
}

// ---------------- K3b: per-rxn min scale (mscale computed inline per edge) ----
__global__ void k_rscale(const float* __restrict__ x,
                         const int* __restrict__ met_sub,
                         const int* __restrict__ rxn_sub)
{
    int e = blockIdx.x * blockDim.x + threadIdx.x;
    if (e >= E_SUB) return;
    int   m    = met_sub[e];
    float tot  = g_totcons[m];
    float conc = x[m * 8 + 3];
    float sc   = (tot > 1e-12f) ? fminf(conc / tot, 1.0f) : 1.0f;
    atomicMin(reinterpret_cast<int*>(&g_rscale[rxn_sub[e]]), __float_as_int(sc));
}

// ---------------- K4: signed contributions -> dxdt (scale applied at use) -----
__global__ void k_contrib(const int* __restrict__ met_sub,
                          const int* __restrict__ rxn_sub,
                          const float* __restrict__ sto_sub,
                          const int* __restrict__ met_prod,
                          const int* __restrict__ rxn_prod,
                          const float* __restrict__ sto_prod,
                          float* __restrict__ out)
{
    int i = blockIdx.x * blockDim.x + threadIdx.x;
    if (i >= E_SUB + E_PROD) return;
    int m; float sto; int r;
    if (i < E_SUB) {
        m = met_sub[i];  r = rxn_sub[i];  sto = -sto_sub[i];
    } else {
        int e = i - E_SUB;
        m = met_prod[e]; r = rxn_prod[e]; sto = sto_prod[e];
    }
    float c = sto * g_v[r] * g_rscale[r];
    atomicAdd(&out[m], c);
}

// ---------------- launch ------------------------------------------------------
extern "C" void kernel_launch(void* const* d_in, const int* in_sizes, int n_in,
                              void* d_out, int out_size)
{
    const float* x        = (const float*)d_in[0];
    const int*   met_sub  = (const int*)  d_in[1];
    const int*   rxn_sub  = (const int*)  d_in[2];
    const float* sto_sub  = (const float*)d_in[3];
    const int*   met_prod = (const int*)  d_in[4];
    const int*   rxn_prod = (const int*)  d_in[5];
    const float* sto_prod = (const float*)d_in[6];
    const float* W1       = (const float*)d_in[7];
    const float* b1       = (const float*)d_in[8];
    const float* W2       = (const float*)d_in[9];
    const float* b2       = (const float*)d_in[10];
    const float* V1       = (const float*)d_in[11];
    const float* c1       = (const float*)d_in[12];
    const float* V2       = (const float*)d_in[13];
    const float* c2       = (const float*)d_in[14];
    const float* log_k    = (const float*)d_in[15];
    float* out = (float*)d_out;

    k_init<<<2048, 256>>>(out);

    k_edge_mlp<<<(E_SUB + 127) / 128, 128>>>(x, met_sub, rxn_sub, sto_sub, W1, b1, W2, b2);

    k_rxn_mlp<<<(N_RXN + 127) / 128, 128>>>(V1, c1, V2, c2, log_k);

    k_totcons<<<(E_SUB + 255) / 256, 256>>>(met_sub, rxn_sub, sto_sub);

    k_rscale<<<(E_SUB + 255) / 256, 256>>>(x, met_sub, rxn_sub);

    k_contrib<<<(E_SUB + E_PROD + 255) / 256, 256>>>(
        met_sub, rxn_sub, sto_sub, met_prod, rxn_prod, sto_prod, out);
}

// round 3
// speedup vs baseline: 1.4093x; 1.3961x over previous
#include <cuda_runtime.h>
#include <math.h>

#define N_MET   100000
#define N_RXN   200000
#define E_SUB   400000
#define E_PROD  400000
#define HIDDEN  128
#define MSG     64
#define DT      0.01f

#define SCAN_BS 512
#define NB1     ((N_RXN + SCAN_BS - 1) / SCAN_BS)   // 391

#define LDT 132     // smem stride (floats) for T tile, conflict-free A-frag loads
#define LDM 136     // smem stride (floats) for M tile, conflict-free B-frag loads
#define K2_TILE 64
#define K2_NBLK (N_RXN / K2_TILE)                   // 3125, exact

// smem floats: UWB(512) + c1(128) + V2(128) + bb(128) + cnt(64) + ext(64) + T(64*LDT) + M(128*LDM)
#define K2_SMEM_FLOATS (512 + 128 + 128 + 128 + 64 + 64 + K2_TILE * LDT + HIDDEN * LDM)
#define K2_SMEM_BYTES  (K2_SMEM_FLOATS * 4)

// ---------------- scratch (device globals; no allocation allowed) -------------
__device__ int   g_cnt[N_RXN];
__device__ int   g_roff[N_RXN];
__device__ int   g_part[NB1];
__device__ int   g_partx[NB1];
__device__ int   g_start[N_RXN];
__device__ int   g_cursor[N_RXN];
__device__ int   g_eidx[E_SUB];
__device__ float g_M[HIDDEN * HIDDEN];   // W2 @ V1  (128x128)
__device__ float g_bb[HIDDEN];           // b2 @ V1
__device__ float g_v[N_RXN];
__device__ float g_rscale[N_RXN];
__device__ float g_totcons[N_MET];

__device__ __forceinline__ float tanh_fast(float x) {
    float y; asm("tanh.approx.f32 %0, %1;" : "=f"(y) : "f"(x)); return y;
}
__device__ __forceinline__ unsigned cvt_tf32(float f) {
    unsigned u; asm("cvt.rna.tf32.f32 %0, %1;" : "=r"(u) : "f"(f)); return u;
}

// ---------------- K0: init ----------------------------------------------------
__global__ void k_init(float* __restrict__ out) {
    int i = blockIdx.x * blockDim.x + threadIdx.x;
    int stride = gridDim.x * blockDim.x;
    for (int p = i; p < N_RXN; p += stride) g_cnt[p] = 0;
    for (int p = i; p < N_MET; p += stride) { g_totcons[p] = 0.f; out[p] = 0.f; }
}

// ---------------- K_w: fold weights: M = W2@V1, bb = b2@V1 --------------------
__global__ void k_weights(const float* __restrict__ W2,
                          const float* __restrict__ V1,
                          const float* __restrict__ b2)
{
    int j = blockIdx.x;       // 0..128 (128 = bb row)
    int n = threadIdx.x;      // 0..127
    if (j < HIDDEN) {
        float acc = 0.f;
        for (int k = 0; k < MSG; k++)
            acc = fmaf(W2[j * MSG + k], V1[k * HIDDEN + n], acc);
        g_M[j * HIDDEN + n] = acc;
    } else {
        float acc = 0.f;
        for (int k = 0; k < MSG; k++)
            acc = fmaf(b2[k], V1[k * HIDDEN + n], acc);
        g_bb[n] = acc;
    }
}

// ---------------- CSR build ---------------------------------------------------
__global__ void k_hist(const int* __restrict__ rxn_sub) {
    int e = blockIdx.x * blockDim.x + threadIdx.x;
    if (e < E_SUB) atomicAdd(&g_cnt[rxn_sub[e]], 1);
}

__global__ void k_scan1() {
    __shared__ int s[SCAN_BS];
    int b = blockIdx.x, t = threadIdx.x;
    int i = b * SCAN_BS + t;
    int v = (i < N_RXN) ? g_cnt[i] : 0;
    s[t] = v; __syncthreads();
    for (int off = 1; off < SCAN_BS; off <<= 1) {
        int x = (t >= off) ? s[t - off] : 0;
        __syncthreads();
        s[t] += x;
        __syncthreads();
    }
    if (i < N_RXN) g_roff[i] = s[t] - v;           // exclusive within block
    if (t == SCAN_BS - 1) g_part[b] = s[t];        // block total
}

__global__ void k_scan2() {
    __shared__ int s[SCAN_BS];
    int t = threadIdx.x;
    int v = (t < NB1) ? g_part[t] : 0;
    s[t] = v; __syncthreads();
    for (int off = 1; off < SCAN_BS; off <<= 1) {
        int x = (t >= off) ? s[t - off] : 0;
        __syncthreads();
        s[t] += x;
        __syncthreads();
    }
    if (t < NB1) g_partx[t] = s[t] - v;            // exclusive over blocks
}

__global__ void k_start() {
    int r = blockIdx.x * blockDim.x + threadIdx.x;
    if (r >= N_RXN) return;
    int st = g_roff[r] + g_partx[r >> 9];          // 512 = 2^9
    g_start[r]  = st;
    g_cursor[r] = st;
}

__global__ void k_scatter(const int* __restrict__ rxn_sub) {
    int e = blockIdx.x * blockDim.x + threadIdx.x;
    if (e >= E_SUB) return;
    int pos = atomicAdd(&g_cursor[rxn_sub[e]], 1);
    g_eidx[pos] = e;
}

// ---------------- K2: fused gather + layer1 + tf32 GEMM + epilogue ------------
__global__ __launch_bounds__(128)
void k2_gemm(const float* __restrict__ x,
             const int*   __restrict__ met_sub,
             const float* __restrict__ sto_sub,
             const float* __restrict__ W1,
             const float* __restrict__ b1,
             const float* __restrict__ c1v,
             const float* __restrict__ V2,
             const float* __restrict__ c2,
             const float* __restrict__ log_k)
{
    extern __shared__ float sm[];
    float4*   sUWB = (float4*)sm;                  // 128 x {U,W,B,pad}
    float*    sc1  = sm + 512;
    float*    sV2  = sc1 + 128;
    float*    sbb  = sV2 + 128;
    float*    scnt = sbb + 128;                    // 64
    float*    sext = scnt + 64;                    // 64
    float*    sT   = sext + 64;                    // 64*LDT (tf32 bits as float)
    unsigned* sM   = (unsigned*)(sT + K2_TILE * LDT); // 128*LDM tf32 bits

    int tid = threadIdx.x, blk = blockIdx.x;

    // stage weights & biases
    {
        sUWB[tid] = make_float4(W1[tid], W1[HIDDEN + tid], b1[tid], 0.f);
        sc1[tid]  = c1v[tid];
        sV2[tid]  = V2[tid];
        sbb[tid]  = g_bb[tid];
    }
    for (int i = tid; i < HIDDEN * HIDDEN; i += 128) {
        int rw = i >> 7, cl = i & 127;
        sM[rw * LDM + cl] = cvt_tf32(g_M[i]);
    }
    __syncthreads();

    // ---- gather + layer-1: 128 threads = 64 rows x 2 halves ----
    {
        int row = tid >> 1, half = tid & 1, j0 = half * 64;
        int r = blk * K2_TILE + row;
        int s = g_start[r], c = g_cnt[r];
        float acc[64];
        #pragma unroll
        for (int j = 0; j < 64; j++) acc[j] = 0.f;
        float exts = 0.f;
        for (int e = 0; e < c; e++) {
            int   idx = g_eidx[s + e];
            int   met = met_sub[idx];
            float sto = sto_sub[idx];
            float a   = x[met * 8 + 3];
            if (half == 0) exts += x[met * 8 + 4];
            #pragma unroll
            for (int j = 0; j < 64; j++) {
                float4 uwb = sUWB[j0 + j];
                acc[j] += tanh_fast(fmaf(a, uwb.x, fmaf(sto, uwb.y, uwb.z)));
            }
        }
        #pragma unroll
        for (int j = 0; j < 64; j++)
            sT[row * LDT + j0 + j] = __uint_as_float(cvt_tf32(acc[j]));
        if (half == 0) { scnt[row] = (float)c; sext[row] = exts; }
    }
    __syncthreads();

    // ---- mma phase: 4 warps x 16 rows each ----
    int w = tid >> 5, lane = tid & 31, gid = lane >> 2, tig = lane & 3;

    unsigned afr[16][4];
    #pragma unroll
    for (int kt = 0; kt < 16; kt++) {
        int k = kt * 8;
        afr[kt][0] = __float_as_uint(sT[(w * 16 + gid)     * LDT + k + tig]);
        afr[kt][1] = __float_as_uint(sT[(w * 16 + gid + 8) * LDT + k + tig]);
        afr[kt][2] = __float_as_uint(sT[(w * 16 + gid)     * LDT + k + 4 + tig]);
        afr[kt][3] = __float_as_uint(sT[(w * 16 + gid + 8) * LDT + k + 4 + tig]);
    }
    float cnt0 = scnt[w * 16 + gid], cnt1 = scnt[w * 16 + gid + 8];
    float acc0 = 0.f, acc1 = 0.f;

    for (int nt = 0; nt < 16; nt++) {
        float c0 = 0.f, c1f = 0.f, c2f = 0.f, c3f = 0.f;
        int n0 = nt * 8;
        #pragma unroll
        for (int kt = 0; kt < 16; kt++) {
            unsigned b0  = sM[(kt * 8 + tig)     * LDM + n0 + gid];
            unsigned b1r = sM[(kt * 8 + tig + 4) * LDM + n0 + gid];
            asm volatile(
                "mma.sync.aligned.m16n8k8.row.col.f32.tf32.tf32.f32 "
                "{%0,%1,%2,%3}, {%4,%5,%6,%7}, {%8,%9}, {%0,%1,%2,%3};"
                : "+f"(c0), "+f"(c1f), "+f"(c2f), "+f"(c3f)
                : "r"(afr[kt][0]), "r"(afr[kt][1]), "r"(afr[kt][2]), "r"(afr[kt][3]),
                  "r"(b0), "r"(b1r));
        }
        int col0 = n0 + 2 * tig, col1 = col0 + 1;
        float bi0 = sc1[col0], bi1 = sc1[col1];
        float bb0 = sbb[col0], bb1 = sbb[col1];
        float v0  = sV2[col0], v1  = sV2[col1];
        acc0 += tanh_fast(fmaf(cnt0, bb0, c0)  + bi0) * v0
              + tanh_fast(fmaf(cnt0, bb1, c1f) + bi1) * v1;
        acc1 += tanh_fast(fmaf(cnt1, bb0, c2f) + bi0) * v0
              + tanh_fast(fmaf(cnt1, bb1, c3f) + bi1) * v1;
    }

    acc0 += __shfl_xor_sync(0xffffffffu, acc0, 1);
    acc0 += __shfl_xor_sync(0xffffffffu, acc0, 2);
    acc1 += __shfl_xor_sync(0xffffffffu, acc1, 1);
    acc1 += __shfl_xor_sync(0xffffffffu, acc1, 2);

    if (tig == 0) {
        float c2s = c2[0];
        int r0 = blk * K2_TILE + w * 16 + gid;
        {
            float z    = acc0 + c2s;
            float base = fmaxf(z, 0.f) + log1pf(expf(-fabsf(z)));
            float extm = sext[w * 16 + gid] / fmaxf(scnt[w * 16 + gid], 1.f);
            g_v[r0]      = exp10f(log_k[r0]) * extm * base;
            g_rscale[r0] = 1.f;
        }
        int r1 = r0 + 8;
        {
            float z    = acc1 + c2s;
            float base = fmaxf(z, 0.f) + log1pf(expf(-fabsf(z)));
            float extm = sext[w * 16 + gid + 8] / fmaxf(scnt[w * 16 + gid + 8], 1.f);
            g_v[r1]      = exp10f(log_k[r1]) * extm * base;
            g_rscale[r1] = 1.f;
        }
    }
}

// ---------------- small scatter kernels (unchanged, proven cheap) -------------
__global__ void k_totcons(const int* __restrict__ met_sub,
                          const int* __restrict__ rxn_sub,
                          const float* __restrict__ sto_sub)
{
    int e = blockIdx.x * blockDim.x + threadIdx.x;
    if (e >= E_SUB) return;
    float c = sto_sub[e] * g_v[rxn_sub[e]] * DT;
    atomicAdd(&g_totcons[met_sub[e]], c);
}

__global__ void k_rscale(const float* __restrict__ x,
                         const int* __restrict__ met_sub,
                         const int* __restrict__ rxn_sub)
{
    int e = blockIdx.x * blockDim.x + threadIdx.x;
    if (e >= E_SUB) return;
    int   m    = met_sub[e];
    float tot  = g_totcons[m];
    float conc = x[m * 8 + 3];
    float sc   = (tot > 1e-12f) ? fminf(conc / tot, 1.0f) : 1.0f;
    atomicMin(reinterpret_cast<int*>(&g_rscale[rxn_sub[e]]), __float_as_int(sc));
}

__global__ void k_contrib(const int* __restrict__ met_sub,
                          const int* __restrict__ rxn_sub,
                          const float* __restrict__ sto_sub,
                          const int* __restrict__ met_prod,
                          const int* __restrict__ rxn_prod,
                          const float* __restrict__ sto_prod,
                          float* __restrict__ out)
{
    int i = blockIdx.x * blockDim.x + threadIdx.x;
    if (i >= E_SUB + E_PROD) return;
    int m, r; float sto;
    if (i < E_SUB) {
        m = met_sub[i];  r = rxn_sub[i];  sto = -sto_sub[i];
    } else {
        int e = i - E_SUB;
        m = met_prod[e]; r = rxn_prod[e]; sto = sto_prod[e];
    }
    atomicAdd(&out[m], sto * g_v[r] * g_rscale[r]);
}

// ---------------- launch ------------------------------------------------------
extern "C" void kernel_launch(void* const* d_in, const int* in_sizes, int n_in,
                              void* d_out, int out_size)
{
    const float* x        = (const float*)d_in[0];
    const int*   met_sub  = (const int*)  d_in[1];
    const int*   rxn_sub  = (const int*)  d_in[2];
    const float* sto_sub  = (const float*)d_in[3];
    const int*   met_prod = (const int*)  d_in[4];
    const int*   rxn_prod = (const int*)  d_in[5];
    const float* sto_prod = (const float*)d_in[6];
    const float* W1       = (const float*)d_in[7];
    const float* b1       = (const float*)d_in[8];
    const float* W2       = (const float*)d_in[9];
    const float* b2       = (const float*)d_in[10];
    const float* V1       = (const float*)d_in[11];
    const float* c1       = (const float*)d_in[12];
    const float* V2       = (const float*)d_in[13];
    const float* c2       = (const float*)d_in[14];
    const float* log_k    = (const float*)d_in[15];
    float* out = (float*)d_out;

    cudaFuncSetAttribute(k2_gemm, cudaFuncAttributeMaxDynamicSharedMemorySize,
                         K2_SMEM_BYTES);

    k_init<<<512, 512>>>(out);
    k_weights<<<HIDDEN + 1, HIDDEN>>>(W2, V1, b2);

    k_hist<<<(E_SUB + 255) / 256, 256>>>(rxn_sub);
    k_scan1<<<NB1, SCAN_BS>>>();
    k_scan2<<<1, SCAN_BS>>>();
    k_start<<<(N_RXN + 255) / 256, 256>>>();
    k_scatter<<<(E_SUB + 255) / 256, 256>>>(rxn_sub);

    k2_gemm<<<K2_NBLK, 128, K2_SMEM_BYTES>>>(x, met_sub, sto_sub,
                                             W1, b1, c1, V2, c2, log_k);

    k_totcons<<<(E_SUB + 255) / 256, 256>>>(met_sub, rxn_sub, sto_sub);
    k_rscale<<<(E_SUB + 255) / 256, 256>>>(x, met_sub, rxn_sub);
    k_contrib<<<(E_SUB + E_PROD + 255) / 256, 256>>>(
        met_sub, rxn_sub, sto_sub, met_prod, rxn_prod, sto_prod, out);
}